// round 4
// baseline (speedup 1.0000x reference)
#include <cuda_runtime.h>

// Matern-3/2 Gram matrix, fused: out[n,m] = s^2 (1+v) exp(-v),
// v = sqrt(3) * sqrt(max(x2[n]+z2[m]-2*dot(X[n],Z[m]), 1e-12)) / lengthscale
//
// Round 1: SIMT fp32 tiled GEMM (128x128x64, 8x8 register micro-tile) with
// fully fused epilogue. Norms precomputed into __device__ scratch.

#define BN 128   // X rows per CTA
#define BM 128   // Z rows per CTA
#define BK 32    // K chunk (D=64 -> 2 chunks)
#define LDM 132  // padded smem row length (floats)
#define D_DIM 64

__device__ float g_x2[8192];
__device__ float g_z2[4096];

__global__ void norms_kernel(const float* __restrict__ X,
                             const float* __restrict__ Z,
                             int N, int M) {
    int t = blockIdx.x * blockDim.x + threadIdx.x;
    const float* src;
    float* dst;
    if (t < N) {
        src = X + (size_t)t * D_DIM;
        dst = &g_x2[t];
    } else if (t < N + M) {
        src = Z + (size_t)(t - N) * D_DIM;
        dst = &g_z2[t - N];
    } else {
        return;
    }
    const float4* s4 = (const float4*)src;
    float s = 0.f;
#pragma unroll
    for (int i = 0; i < D_DIM / 4; ++i) {
        float4 v = s4[i];
        s = fmaf(v.x, v.x, s);
        s = fmaf(v.y, v.y, s);
        s = fmaf(v.z, v.z, s);
        s = fmaf(v.w, v.w, s);
    }
    *dst = s;
}

__device__ __forceinline__ float matern_val(float dot, float xn, float zn,
                                            float c, float s2) {
    float sq = fmaxf(fmaf(-2.0f, dot, xn + zn), 1e-12f);
    float v = c * sqrtf(sq);
    return s2 * (1.0f + v) * __expf(-v);
}

__global__ __launch_bounds__(256, 2)
void matern_kernel(const float* __restrict__ X, const float* __restrict__ Z,
                   const float* __restrict__ sigma,
                   const float* __restrict__ lengthscale,
                   float* __restrict__ out, int N, int M) {
    __shared__ float Xs[BK][LDM];  // K-major: Xs[k][row]
    __shared__ float Zs[BK][LDM];

    const int tid = threadIdx.x;
    const int tx = tid & 15;   // column group (M dir)
    const int ty = tid >> 4;   // row group (N dir)

    const float* Xblk = X + (size_t)(blockIdx.y * BN) * D_DIM;
    const float* Zblk = Z + (size_t)(blockIdx.x * BM) * D_DIM;

    float acc[8][8];
#pragma unroll
    for (int i = 0; i < 8; ++i)
#pragma unroll
        for (int j = 0; j < 8; ++j) acc[i][j] = 0.0f;

    for (int kk = 0; kk < D_DIM; kk += BK) {
        // --- load 128x32 X tile and 128x32 Z tile, transposed into smem ---
        // 1024 float4 slots per tile; slot s: row = s>>3, k = (s&7)*4
#pragma unroll
        for (int it = 0; it < 4; ++it) {
            int s = tid + it * 256;
            int row = s >> 3;
            int k = (s & 7) << 2;
            float4 vx = *(const float4*)(Xblk + (size_t)row * D_DIM + kk + k);
            float4 vz = *(const float4*)(Zblk + (size_t)row * D_DIM + kk + k);
            Xs[k + 0][row] = vx.x;
            Xs[k + 1][row] = vx.y;
            Xs[k + 2][row] = vx.z;
            Xs[k + 3][row] = vx.w;
            Zs[k + 0][row] = vz.x;
            Zs[k + 1][row] = vz.y;
            Zs[k + 2][row] = vz.z;
            Zs[k + 3][row] = vz.w;
        }
        __syncthreads();

        // --- 8x8 register micro-tile over the K chunk ---
#pragma unroll 8
        for (int k = 0; k < BK; ++k) {
            float4 a0 = *(const float4*)&Xs[k][ty * 4];
            float4 a1 = *(const float4*)&Xs[k][64 + ty * 4];
            float4 b0 = *(const float4*)&Zs[k][tx * 4];
            float4 b1 = *(const float4*)&Zs[k][64 + tx * 4];
            float a[8] = {a0.x, a0.y, a0.z, a0.w, a1.x, a1.y, a1.z, a1.w};
            float b[8] = {b0.x, b0.y, b0.z, b0.w, b1.x, b1.y, b1.z, b1.w};
#pragma unroll
            for (int i = 0; i < 8; ++i)
#pragma unroll
                for (int j = 0; j < 8; ++j)
                    acc[i][j] = fmaf(a[i], b[j], acc[i][j]);
        }
        __syncthreads();
    }

    // --- fused epilogue ---
    const float ls = *lengthscale;
    const float sg = *sigma;
    const float c = 1.7320508075688772f / ls;  // sqrt(3)/lengthscale
    const float s2 = sg * sg;

    const int row0 = blockIdx.y * BN + ty * 4;
    const int col0 = blockIdx.x * BM + tx * 4;

    float zn[8];
#pragma unroll
    for (int j = 0; j < 4; ++j) {
        zn[j] = g_z2[col0 + j];
        zn[j + 4] = g_z2[col0 + 64 + j];
    }

#pragma unroll
    for (int i = 0; i < 8; ++i) {
        int r = row0 + ((i < 4) ? i : (60 + i));  // i>=4: row0 + 64 + (i-4)
        float xn = g_x2[r];
        float* orow = out + (size_t)r * M;

        float4 o;
        o.x = matern_val(acc[i][0], xn, zn[0], c, s2);
        o.y = matern_val(acc[i][1], xn, zn[1], c, s2);
        o.z = matern_val(acc[i][2], xn, zn[2], c, s2);
        o.w = matern_val(acc[i][3], xn, zn[3], c, s2);
        *(float4*)(orow + col0) = o;

        o.x = matern_val(acc[i][4], xn, zn[4], c, s2);
        o.y = matern_val(acc[i][5], xn, zn[5], c, s2);
        o.z = matern_val(acc[i][6], xn, zn[6], c, s2);
        o.w = matern_val(acc[i][7], xn, zn[7], c, s2);
        *(float4*)(orow + col0 + 64) = o;
    }
}

extern "C" void kernel_launch(void* const* d_in, const int* in_sizes, int n_in,
                              void* d_out, int out_size) {
    const float* X = (const float*)d_in[0];
    const float* Z = (const float*)d_in[1];
    const float* sigma = (const float*)d_in[2];
    const float* lengthscale = (const float*)d_in[3];
    float* out = (float*)d_out;

    int N = in_sizes[0] / D_DIM;  // 8192
    int M = in_sizes[1] / D_DIM;  // 4096

    int nt = N + M;
    norms_kernel<<<(nt + 255) / 256, 256>>>(X, Z, N, M);

    dim3 grid(M / BM, N / BN);  // (32, 64)
    matern_kernel<<<grid, 256>>>(X, Z, sigma, lengthscale, out, N, M);
}

// round 9
// speedup vs baseline: 1.3992x; 1.3992x over previous
#include <cuda_runtime.h>
#include <cuda_bf16.h>
#include <cstdint>

// Matern-3/2 Gram via bf16 split-K HMMA (mma.sync m16n8k16) + fused epilogue.
//   dot(X[n],Z[m]) ~fp32 via K-packed bf16 split:
//     Xc = [hi(X) | lo(X) | hi(X)]  (K=192)
//     Zc = [hi(Z) | hi(Z) | lo(Z)]
//   out = s^2 (1+v) exp(-v), v = sqrt(3)*sqrt(max(x2+z2-2dot,1e-12))/ls
// NOTE: tcgen05 is unusable here (harness emits compute_103 PTX, tcgen05 is
// sm_103a-only at PTX level) -> Ampere-class mma.sync path.

#define D_DIM 64
#define KC    192
#define NMAX  8192
#define MMAX  4096

#define ROWB  384          // bytes per row in gmem scratch (192 bf16)
#define LDSW  400          // padded bytes per smem row (conflict-free LDSM)

__device__ __align__(16) __nv_bfloat16 g_Xc[NMAX * KC];   // 3 MB
__device__ __align__(16) __nv_bfloat16 g_Zc[MMAX * KC];   // 1.5 MB
__device__ float g_x2[NMAX];
__device__ float g_z2[MMAX];

// smem layout
#define SM_XN 0                    // 128 floats
#define SM_ZN 512                  // 128 floats
#define SM_A  1024                 // 128 x LDSW bytes
#define SM_B  (SM_A + 128 * LDSW)  // 128 x LDSW bytes
#define SM_TOTAL (SM_B + 128 * LDSW)

__device__ __forceinline__ uint32_t s2u(const void* p) {
    uint32_t a;
    asm("{ .reg .u64 t; cvta.to.shared.u64 t, %1; cvt.u32.u64 %0, t; }"
        : "=r"(a) : "l"(p));
    return a;
}
__device__ __forceinline__ float fsqrt_ap(float x) {
    float r; asm("sqrt.approx.f32 %0, %1;" : "=f"(r) : "f"(x)); return r;
}
__device__ __forceinline__ float fex2(float x) {
    float r; asm("ex2.approx.f32 %0, %1;" : "=f"(r) : "f"(x)); return r;
}

#define LDSM_X4(r0, r1, r2, r3, addr)                                         \
    asm volatile("ldmatrix.sync.aligned.m8n8.x4.shared.b16 {%0,%1,%2,%3}, [%4];" \
                 : "=r"(r0), "=r"(r1), "=r"(r2), "=r"(r3) : "r"(addr))

#define MMA16816(c, a, b0v, b1v)                                              \
    asm volatile("mma.sync.aligned.m16n8k16.row.col.f32.bf16.bf16.f32 "       \
                 "{%0,%1,%2,%3}, {%4,%5,%6,%7}, {%8,%9}, {%0,%1,%2,%3};"      \
                 : "+f"((c)[0]), "+f"((c)[1]), "+f"((c)[2]), "+f"((c)[3])     \
                 : "r"((a)[0]), "r"((a)[1]), "r"((a)[2]), "r"((a)[3]),        \
                   "r"(b0v), "r"(b1v))

// ---- prep: bf16 hi/lo split + row norms ----
__global__ void convert_kernel(const float* __restrict__ X,
                               const float* __restrict__ Z, int N, int M) {
    int t = blockIdx.x * blockDim.x + threadIdx.x;
    const float* src; __nv_bfloat16* dst; float* nd; bool isX;
    if (t < N)          { src = X + (size_t)t * D_DIM; dst = g_Xc + (size_t)t * KC; nd = &g_x2[t]; isX = true; }
    else if (t < N + M) { int r = t - N; src = Z + (size_t)r * D_DIM; dst = g_Zc + (size_t)r * KC; nd = &g_z2[r]; isX = false; }
    else return;
    float s = 0.f;
#pragma unroll
    for (int k = 0; k < D_DIM; k += 2) {
        float2 v = *(const float2*)(src + k);
        s = fmaf(v.x, v.x, s); s = fmaf(v.y, v.y, s);
        __nv_bfloat16 hx = __float2bfloat16(v.x);
        __nv_bfloat16 hy = __float2bfloat16(v.y);
        __nv_bfloat162 hi; hi.x = hx; hi.y = hy;
        __nv_bfloat162 lo;
        lo.x = __float2bfloat16(v.x - __bfloat162float(hx));
        lo.y = __float2bfloat16(v.y - __bfloat162float(hy));
        *(__nv_bfloat162*)(dst + k) = hi;
        *(__nv_bfloat162*)(dst + 64 + k)  = isX ? lo : hi;
        *(__nv_bfloat162*)(dst + 128 + k) = isX ? hi : lo;
    }
    *nd = s;
}

// ---- main: 128x128 CTA tile, 8 warps (4m x 2n), warp = 32x64 ----
__global__ __launch_bounds__(256, 1)
void matern_hmma_kernel(const float* __restrict__ sigma,
                        const float* __restrict__ lengthscale,
                        float* __restrict__ out, int M) {
    extern __shared__ char smem[];
    const uint32_t sb = s2u(smem);
    const int tid = threadIdx.x;
    const int lane = tid & 31, wid = tid >> 5;
    const int wm = wid & 3;      // 4 m-blocks of 32 rows
    const int wn = wid >> 2;     // 2 n-blocks of 64 cols
    const int bn = blockIdx.y, bm = blockIdx.x;

    // row norms into smem
    if (tid < 128)
        ((float*)(smem + SM_XN))[tid] = g_x2[bn * 128 + tid];
    else
        ((float*)(smem + SM_ZN))[tid - 128] = g_z2[bm * 128 + (tid - 128)];

    // tile loads: 128 rows x 384B each for A and B (padded to LDSW in smem)
    {
        const char* As = (const char*)(g_Xc + (size_t)(bn * 128) * KC);
        const char* Bs = (const char*)(g_Zc + (size_t)(bm * 128) * KC);
#pragma unroll
        for (int it = 0; it < 12; ++it) {
            int i = tid + it * 256;      // 0..3071
            int row = i / 24;
            int c8 = i - row * 24;       // 16B chunk within row
            *(uint4*)(smem + SM_A + row * LDSW + c8 * 16) =
                *(const uint4*)(As + (size_t)row * ROWB + c8 * 16);
            *(uint4*)(smem + SM_B + row * LDSW + c8 * 16) =
                *(const uint4*)(Bs + (size_t)row * ROWB + c8 * 16);
        }
    }
    __syncthreads();

    // per-lane ldmatrix base addresses
    const int l8 = lane & 7, sel = lane >> 3;
    uint32_t a_addr[2], b_addr[4];
#pragma unroll
    for (int mt = 0; mt < 2; ++mt) {
        int row = wm * 32 + mt * 16 + ((sel & 1) << 3) + l8;
        a_addr[mt] = sb + SM_A + row * LDSW + ((sel >> 1) << 4);
    }
#pragma unroll
    for (int p = 0; p < 4; ++p) {
        int n = wn * 64 + p * 16 + ((sel >> 1) << 3) + l8;
        b_addr[p] = sb + SM_B + n * LDSW + ((sel & 1) << 4);
    }

    float acc[2][8][4];
#pragma unroll
    for (int mt = 0; mt < 2; ++mt)
#pragma unroll
        for (int nt = 0; nt < 8; ++nt)
#pragma unroll
            for (int q = 0; q < 4; ++q) acc[mt][nt][q] = 0.0f;

    // K = 192 = 12 k-steps of 16
#pragma unroll
    for (int ks = 0; ks < 12; ++ks) {
        uint32_t a[2][4], b[4][4];
        LDSM_X4(a[0][0], a[0][1], a[0][2], a[0][3], a_addr[0] + ks * 32);
        LDSM_X4(a[1][0], a[1][1], a[1][2], a[1][3], a_addr[1] + ks * 32);
#pragma unroll
        for (int p = 0; p < 4; ++p)
            LDSM_X4(b[p][0], b[p][1], b[p][2], b[p][3], b_addr[p] + ks * 32);
#pragma unroll
        for (int mt = 0; mt < 2; ++mt)
#pragma unroll
            for (int p = 0; p < 4; ++p) {
                MMA16816(acc[mt][2 * p], a[mt], b[p][0], b[p][1]);
                MMA16816(acc[mt][2 * p + 1], a[mt], b[p][2], b[p][3]);
            }
    }

    // ---- fused Matern epilogue ----
    const float ls = *lengthscale;
    const float sg = *sigma;
    const float cc = 1.7320508075688772f / ls;
    const float s2v = sg * sg;
    const float NL2E = -1.4426950408889634f;

    const int qrow = lane >> 2;          // 0..7
    const int qcol = (lane & 3) << 1;    // 0,2,4,6

    const float* xnS = (const float*)(smem + SM_XN);
    const float* znS = (const float*)(smem + SM_ZN);

    float2 znp[8];
#pragma unroll
    for (int nt = 0; nt < 8; ++nt)
        znp[nt] = *(const float2*)(znS + wn * 64 + nt * 8 + qcol);

#pragma unroll
    for (int mt = 0; mt < 2; ++mt) {
#pragma unroll
        for (int h = 0; h < 2; ++h) {
            const int rloc = wm * 32 + mt * 16 + h * 8 + qrow;
            const float xn = xnS[rloc];
            float* orow = out + (size_t)(bn * 128 + rloc) * M + bm * 128;
#pragma unroll
            for (int nt = 0; nt < 8; ++nt) {
                float d0 = acc[mt][nt][2 * h];
                float d1 = acc[mt][nt][2 * h + 1];
                float sq0 = fmaxf(fmaf(-2.0f, d0, xn + znp[nt].x), 1e-12f);
                float sq1 = fmaxf(fmaf(-2.0f, d1, xn + znp[nt].y), 1e-12f);
                float v0 = cc * fsqrt_ap(sq0);
                float v1 = cc * fsqrt_ap(sq1);
                float e0 = fex2(NL2E * v0);
                float e1 = fex2(NL2E * v1);
                float2 o;
                o.x = s2v * (1.0f + v0) * e0;
                o.y = s2v * (1.0f + v1) * e1;
                *(float2*)(orow + wn * 64 + nt * 8 + qcol) = o;
            }
        }
    }
}

extern "C" void kernel_launch(void* const* d_in, const int* in_sizes, int n_in,
                              void* d_out, int out_size) {
    const float* X = (const float*)d_in[0];
    const float* Z = (const float*)d_in[1];
    const float* sigma = (const float*)d_in[2];
    const float* lengthscale = (const float*)d_in[3];
    float* out = (float*)d_out;

    int N = in_sizes[0] / D_DIM;   // 8192
    int M = in_sizes[1] / D_DIM;   // 4096

    convert_kernel<<<(N + M + 127) / 128, 128>>>(X, Z, N, M);

    cudaFuncSetAttribute(matern_hmma_kernel,
                         cudaFuncAttributeMaxDynamicSharedMemorySize, SM_TOTAL);
    dim3 grid(M / 128, N / 128);   // (32, 64)
    matern_hmma_kernel<<<grid, 256, SM_TOTAL>>>(sigma, lengthscale, out, M);
}

// round 10
// speedup vs baseline: 1.6391x; 1.1715x over previous
#include <cuda_runtime.h>
#include <cuda_bf16.h>
#include <cstdint>

// Matern-3/2 Gram via bf16 split-K HMMA (mma.sync m16n8k16) + fused epilogue.
//   dot(X[n],Z[m]) ~fp32 via K-packed bf16 split:
//     Xc = [hi(X) | lo(X) | hi(X)]  (K=192)
//     Zc = [hi(Z) | hi(Z) | lo(Z)]
//   out = s^2 (1+v) exp(-v), v = sqrt(3)*sqrt(max(x2+z2-2dot,1e-12))/ls
// R9: CTA 256x128, warp tile 64x64 (8 warps), 3-stage cp.async K-pipeline.

#define D_DIM 64
#define KC    192
#define NMAX  8192
#define MMAX  4096

#define ROWB  384           // bytes per row in gmem scratch (192 bf16)
#define LDSW  144           // padded smem row bytes per stage (128 data + 16)
#define ASTG  (256 * LDSW)  // 36864 B per A stage
#define BSTG  (128 * LDSW)  // 18432 B per B stage

__device__ __align__(16) __nv_bfloat16 g_Xc[NMAX * KC];   // 3 MB
__device__ __align__(16) __nv_bfloat16 g_Zc[MMAX * KC];   // 1.5 MB
__device__ float g_x2[NMAX];
__device__ float g_z2[MMAX];

// smem layout
#define SM_XN 0                      // 256 floats
#define SM_ZN 1024                   // 128 floats
#define SM_A  1536                   // 3 stages x 36864
#define SM_B  (SM_A + 3 * ASTG)      // 3 stages x 18432
#define SM_TOTAL (SM_B + 3 * BSTG)   // 167424 B

__device__ __forceinline__ uint32_t s2u(const void* p) {
    uint32_t a;
    asm("{ .reg .u64 t; cvta.to.shared.u64 t, %1; cvt.u32.u64 %0, t; }"
        : "=r"(a) : "l"(p));
    return a;
}
__device__ __forceinline__ float fsqrt_ap(float x) {
    float r; asm("sqrt.approx.f32 %0, %1;" : "=f"(r) : "f"(x)); return r;
}
__device__ __forceinline__ float fex2(float x) {
    float r; asm("ex2.approx.f32 %0, %1;" : "=f"(r) : "f"(x)); return r;
}

#define CP16(dst, src)                                                        \
    asm volatile("cp.async.cg.shared.global [%0], [%1], 16;"                  \
                 :: "r"(dst), "l"(src) : "memory")

#define LDSM_X4(r0, r1, r2, r3, addr)                                         \
    asm volatile("ldmatrix.sync.aligned.m8n8.x4.shared.b16 {%0,%1,%2,%3}, [%4];" \
                 : "=r"(r0), "=r"(r1), "=r"(r2), "=r"(r3) : "r"(addr))

#define MMA16816(c, a, b0v, b1v)                                              \
    asm volatile("mma.sync.aligned.m16n8k16.row.col.f32.bf16.bf16.f32 "       \
                 "{%0,%1,%2,%3}, {%4,%5,%6,%7}, {%8,%9}, {%0,%1,%2,%3};"      \
                 : "+f"((c)[0]), "+f"((c)[1]), "+f"((c)[2]), "+f"((c)[3])     \
                 : "r"((a)[0]), "r"((a)[1]), "r"((a)[2]), "r"((a)[3]),        \
                   "r"(b0v), "r"(b1v))

// ---- prep: bf16 hi/lo split + row norms (4 threads per row) ----
__global__ void convert_kernel(const float* __restrict__ X,
                               const float* __restrict__ Z, int N, int M) {
    int t = blockIdx.x * blockDim.x + threadIdx.x;
    int row = t >> 2, q = t & 3;
    if (row >= N + M) return;
    const float* src; __nv_bfloat16* dst; float* nd; bool isX;
    if (row < N) { src = X + (size_t)row * D_DIM; dst = g_Xc + (size_t)row * KC; nd = &g_x2[row]; isX = true; }
    else { int r = row - N; src = Z + (size_t)r * D_DIM; dst = g_Zc + (size_t)r * KC; nd = &g_z2[r]; isX = false; }
    src += q * 16;
    float s = 0.f;
#pragma unroll
    for (int k = 0; k < 16; k += 2) {
        float2 v = *(const float2*)(src + k);
        s = fmaf(v.x, v.x, s); s = fmaf(v.y, v.y, s);
        __nv_bfloat16 hx = __float2bfloat16(v.x);
        __nv_bfloat16 hy = __float2bfloat16(v.y);
        __nv_bfloat162 hi; hi.x = hx; hi.y = hy;
        __nv_bfloat162 lo;
        lo.x = __float2bfloat16(v.x - __bfloat162float(hx));
        lo.y = __float2bfloat16(v.y - __bfloat162float(hy));
        int kk = q * 16 + k;
        *(__nv_bfloat162*)(dst + kk) = hi;
        *(__nv_bfloat162*)(dst + 64 + kk)  = isX ? lo : hi;
        *(__nv_bfloat162*)(dst + 128 + kk) = isX ? hi : lo;
    }
    s += __shfl_xor_sync(0xffffffffu, s, 1);
    s += __shfl_xor_sync(0xffffffffu, s, 2);
    if (q == 0) *nd = s;
}

// ---- one K=64 stage: 4 k-steps of 16, warp tile 64x64 ----
__device__ __forceinline__ void stage_mma(uint32_t aBase, uint32_t bBase,
                                          const uint32_t* a_off,
                                          const uint32_t* b_off,
                                          float acc[4][8][4]) {
#pragma unroll
    for (int ks = 0; ks < 4; ++ks) {
        uint32_t a[4][4];
#pragma unroll
        for (int mt = 0; mt < 4; ++mt)
            LDSM_X4(a[mt][0], a[mt][1], a[mt][2], a[mt][3],
                    aBase + a_off[mt] + ks * 32);
#pragma unroll
        for (int p = 0; p < 4; ++p) {
            uint32_t b[4];
            LDSM_X4(b[0], b[1], b[2], b[3], bBase + b_off[p] + ks * 32);
#pragma unroll
            for (int mt = 0; mt < 4; ++mt) {
                MMA16816(acc[mt][2 * p], a[mt], b[0], b[1]);
                MMA16816(acc[mt][2 * p + 1], a[mt], b[2], b[3]);
            }
        }
    }
}

// ---- main: 256x128 CTA tile, 8 warps (4m x 2n), warp = 64x64 ----
__global__ __launch_bounds__(256)
void matern_hmma_kernel(const float* __restrict__ sigma,
                        const float* __restrict__ lengthscale,
                        float* __restrict__ out, int M) {
    extern __shared__ char smem[];
    const uint32_t sb = s2u(smem);
    const int tid = threadIdx.x;
    const int lane = tid & 31, wid = tid >> 5;
    const int wm = wid & 3;      // 4 m-blocks of 64 rows
    const int wn = wid >> 2;     // 2 n-blocks of 64 cols
    const int bn = blockIdx.y, bm = blockIdx.x;

    // row norms into smem
    ((float*)(smem + SM_XN))[tid] = g_x2[bn * 256 + tid];
    if (tid < 128)
        ((float*)(smem + SM_ZN))[tid] = g_z2[bm * 128 + tid];

    // 3-stage cp.async tile loads (K chunks of 64 = 128B per row)
    {
        const char* As = (const char*)g_Xc + (size_t)(bn * 256) * ROWB;
        const char* Bs = (const char*)g_Zc + (size_t)(bm * 128) * ROWB;
#pragma unroll
        for (int s3 = 0; s3 < 3; ++s3) {
#pragma unroll
            for (int it = 0; it < 12; ++it) {
                if (it < 8) {                   // A: 2048 chunks
                    int i = tid + it * 256;
                    int row = i >> 3, c = i & 7;
                    CP16(sb + SM_A + s3 * ASTG + row * LDSW + c * 16,
                         As + (size_t)row * ROWB + s3 * 128 + c * 16);
                } else {                        // B: 1024 chunks
                    int j = tid + (it - 8) * 256;
                    int row = j >> 3, c = j & 7;
                    CP16(sb + SM_B + s3 * BSTG + row * LDSW + c * 16,
                         Bs + (size_t)row * ROWB + s3 * 128 + c * 16);
                }
            }
            asm volatile("cp.async.commit_group;" ::: "memory");
        }
    }

    // per-lane ldmatrix offsets (within a stage)
    const int l8 = lane & 7, sel = lane >> 3;
    uint32_t a_off[4], b_off[4];
#pragma unroll
    for (int mt = 0; mt < 4; ++mt) {
        int row = wm * 64 + mt * 16 + ((sel & 1) << 3) + l8;
        a_off[mt] = row * LDSW + ((sel >> 1) << 4);
    }
#pragma unroll
    for (int p = 0; p < 4; ++p) {
        int n = wn * 64 + p * 16 + ((sel >> 1) << 3) + l8;
        b_off[p] = n * LDSW + ((sel & 1) << 4);
    }

    float acc[4][8][4];
#pragma unroll
    for (int mt = 0; mt < 4; ++mt)
#pragma unroll
        for (int nt = 0; nt < 8; ++nt)
#pragma unroll
            for (int q = 0; q < 4; ++q) acc[mt][nt][q] = 0.0f;

    asm volatile("cp.async.wait_group 2;" ::: "memory");
    __syncthreads();
    stage_mma(sb + SM_A, sb + SM_B, a_off, b_off, acc);

    asm volatile("cp.async.wait_group 1;" ::: "memory");
    __syncthreads();
    stage_mma(sb + SM_A + ASTG, sb + SM_B + BSTG, a_off, b_off, acc);

    asm volatile("cp.async.wait_group 0;" ::: "memory");
    __syncthreads();
    stage_mma(sb + SM_A + 2 * ASTG, sb + SM_B + 2 * BSTG, a_off, b_off, acc);

    // ---- fused Matern epilogue ----
    const float ls = *lengthscale;
    const float sg = *sigma;
    const float cc = 1.7320508075688772f / ls;
    const float s2v = sg * sg;
    const float NL2E = -1.4426950408889634f;

    const int qrow = lane >> 2;          // 0..7
    const int qcol = (lane & 3) << 1;    // 0,2,4,6

    const float* xnS = (const float*)(smem + SM_XN);
    const float* znS = (const float*)(smem + SM_ZN);

    float2 znp[8];
#pragma unroll
    for (int nt = 0; nt < 8; ++nt)
        znp[nt] = *(const float2*)(znS + wn * 64 + nt * 8 + qcol);

#pragma unroll
    for (int mt = 0; mt < 4; ++mt) {
#pragma unroll
        for (int h = 0; h < 2; ++h) {
            const int rloc = wm * 64 + mt * 16 + h * 8 + qrow;
            const float xn = xnS[rloc];
            float* orow = out + (size_t)(bn * 256 + rloc) * M + bm * 128;
#pragma unroll
            for (int nt = 0; nt < 8; ++nt) {
                float d0 = acc[mt][nt][2 * h];
                float d1 = acc[mt][nt][2 * h + 1];
                float sq0 = fmaxf(fmaf(-2.0f, d0, xn + znp[nt].x), 1e-12f);
                float sq1 = fmaxf(fmaf(-2.0f, d1, xn + znp[nt].y), 1e-12f);
                float v0 = cc * fsqrt_ap(sq0);
                float v1 = cc * fsqrt_ap(sq1);
                float e0 = fex2(NL2E * v0);
                float e1 = fex2(NL2E * v1);
                float2 o;
                o.x = s2v * (1.0f + v0) * e0;
                o.y = s2v * (1.0f + v1) * e1;
                *(float2*)(orow + wn * 64 + nt * 8 + qcol) = o;
            }
        }
    }
}

extern "C" void kernel_launch(void* const* d_in, const int* in_sizes, int n_in,
                              void* d_out, int out_size) {
    const float* X = (const float*)d_in[0];
    const float* Z = (const float*)d_in[1];
    const float* sigma = (const float*)d_in[2];
    const float* lengthscale = (const float*)d_in[3];
    float* out = (float*)d_out;

    int N = in_sizes[0] / D_DIM;   // 8192
    int M = in_sizes[1] / D_DIM;   // 4096

    convert_kernel<<<((N + M) * 4 + 255) / 256, 256>>>(X, Z, N, M);

    cudaFuncSetAttribute(matern_hmma_kernel,
                         cudaFuncAttributeMaxDynamicSharedMemorySize, SM_TOTAL);
    dim3 grid(M / 128, N / 256);   // (32, 32)
    matern_hmma_kernel<<<grid, 256, SM_TOTAL>>>(sigma, lengthscale, out, M);
}

// round 12
// speedup vs baseline: 1.8196x; 1.1101x over previous
#include <cuda_runtime.h>
#include <cuda_bf16.h>
#include <cstdint>

// Matern-3/2 Gram via bf16 split-K HMMA (mma.sync m16n8k16) + fused epilogue.
//   dot(X[n],Z[m]) ~fp32 via K-packed bf16 split:
//     Xc = [hi(X) | lo(X) | hi(X)]  (K=192)
//     Zc = [hi(Z) | hi(Z) | lo(Z)]
//   out = s^2 (1+v) exp(-v), v = sqrt(3)*sqrt(max(x2+z2-2dot,1e-12))/ls
// R10: CTA 256x128 / 512 thr / 16 warps (warp tile 64x32) for issue hiding;
//      warp-per-row convert kernel.

#define D_DIM 64
#define KC    192
#define NMAX  8192
#define MMAX  4096

#define ROWB  384           // bytes per row in gmem scratch (192 bf16)
#define LDSW  144           // padded smem row bytes per stage (128 data + 16)
#define ASTG  (256 * LDSW)  // 36864 B per A stage
#define BSTG  (128 * LDSW)  // 18432 B per B stage

__device__ __align__(16) __nv_bfloat16 g_Xc[NMAX * KC];   // 3 MB
__device__ __align__(16) __nv_bfloat16 g_Zc[MMAX * KC];   // 1.5 MB
__device__ float g_x2[NMAX];
__device__ float g_z2[MMAX];

// smem layout
#define SM_XN 0                      // 256 floats
#define SM_ZN 1024                   // 128 floats
#define SM_A  1536                   // 3 stages x 36864
#define SM_B  (SM_A + 3 * ASTG)      // 3 stages x 18432
#define SM_TOTAL (SM_B + 3 * BSTG)   // 167424 B

__device__ __forceinline__ uint32_t s2u(const void* p) {
    uint32_t a;
    asm("{ .reg .u64 t; cvta.to.shared.u64 t, %1; cvt.u32.u64 %0, t; }"
        : "=r"(a) : "l"(p));
    return a;
}
__device__ __forceinline__ float fsqrt_ap(float x) {
    float r; asm("sqrt.approx.f32 %0, %1;" : "=f"(r) : "f"(x)); return r;
}
__device__ __forceinline__ float fex2(float x) {
    float r; asm("ex2.approx.f32 %0, %1;" : "=f"(r) : "f"(x)); return r;
}

#define CP16(dst, src)                                                        \
    asm volatile("cp.async.cg.shared.global [%0], [%1], 16;"                  \
                 :: "r"(dst), "l"(src) : "memory")

#define LDSM_X4(r0, r1, r2, r3, addr)                                         \
    asm volatile("ldmatrix.sync.aligned.m8n8.x4.shared.b16 {%0,%1,%2,%3}, [%4];" \
                 : "=r"(r0), "=r"(r1), "=r"(r2), "=r"(r3) : "r"(addr))

#define MMA16816(c, a, b0v, b1v)                                              \
    asm volatile("mma.sync.aligned.m16n8k16.row.col.f32.bf16.bf16.f32 "       \
                 "{%0,%1,%2,%3}, {%4,%5,%6,%7}, {%8,%9}, {%0,%1,%2,%3};"      \
                 : "+f"((c)[0]), "+f"((c)[1]), "+f"((c)[2]), "+f"((c)[3])     \
                 : "r"((a)[0]), "r"((a)[1]), "r"((a)[2]), "r"((a)[3]),        \
                   "r"(b0v), "r"(b1v))

// ---- prep: warp per row; lane owns 2 k-positions (coalesced) ----
__global__ void convert_kernel(const float* __restrict__ X,
                               const float* __restrict__ Z, int N, int M) {
    int t = blockIdx.x * blockDim.x + threadIdx.x;
    int row = t >> 5, lane = t & 31;
    if (row >= N + M) return;
    const float* src; __nv_bfloat16* dst; float* nd; bool isX;
    if (row < N) { src = X + (size_t)row * D_DIM; dst = g_Xc + (size_t)row * KC; nd = &g_x2[row]; isX = true; }
    else { int r = row - N; src = Z + (size_t)r * D_DIM; dst = g_Zc + (size_t)r * KC; nd = &g_z2[r]; isX = false; }

    int k = lane * 2;
    float2 v = *(const float2*)(src + k);
    float s = fmaf(v.x, v.x, v.y * v.y);
#pragma unroll
    for (int d = 16; d > 0; d >>= 1)
        s += __shfl_xor_sync(0xffffffffu, s, d);

    __nv_bfloat16 hx = __float2bfloat16(v.x);
    __nv_bfloat16 hy = __float2bfloat16(v.y);
    __nv_bfloat162 hi; hi.x = hx; hi.y = hy;
    __nv_bfloat162 lo;
    lo.x = __float2bfloat16(v.x - __bfloat162float(hx));
    lo.y = __float2bfloat16(v.y - __bfloat162float(hy));
    *(__nv_bfloat162*)(dst + k) = hi;
    *(__nv_bfloat162*)(dst + 64 + k)  = isX ? lo : hi;
    *(__nv_bfloat162*)(dst + 128 + k) = isX ? hi : lo;
    if (lane == 0) *nd = s;
}

// ---- one K=64 stage: 4 k-steps of 16, warp tile 64x32 ----
__device__ __forceinline__ void stage_mma(uint32_t aBase, uint32_t bBase,
                                          const uint32_t* a_off,
                                          const uint32_t* b_off,
                                          float acc[4][4][4]) {
#pragma unroll
    for (int ks = 0; ks < 4; ++ks) {
        uint32_t a[4][4];
#pragma unroll
        for (int mt = 0; mt < 4; ++mt)
            LDSM_X4(a[mt][0], a[mt][1], a[mt][2], a[mt][3],
                    aBase + a_off[mt] + ks * 32);
#pragma unroll
        for (int p = 0; p < 2; ++p) {
            uint32_t b[4];
            LDSM_X4(b[0], b[1], b[2], b[3], bBase + b_off[p] + ks * 32);
#pragma unroll
            for (int mt = 0; mt < 4; ++mt) {
                MMA16816(acc[mt][2 * p], a[mt], b[0], b[1]);
                MMA16816(acc[mt][2 * p + 1], a[mt], b[2], b[3]);
            }
        }
    }
}

// ---- main: 256x128 CTA tile, 16 warps (4m x 4n), warp = 64x32 ----
__global__ __launch_bounds__(512, 1)
void matern_hmma_kernel(const float* __restrict__ sigma,
                        const float* __restrict__ lengthscale,
                        float* __restrict__ out, int M) {
    extern __shared__ char smem[];
    const uint32_t sb = s2u(smem);
    const int tid = threadIdx.x;
    const int lane = tid & 31, wid = tid >> 5;
    const int wm = wid & 3;      // 4 m-blocks of 64 rows
    const int wn = wid >> 2;     // 4 n-blocks of 32 cols
    const int bn = blockIdx.y, bm = blockIdx.x;

    // row norms into smem
    if (tid < 256)
        ((float*)(smem + SM_XN))[tid] = g_x2[bn * 256 + tid];
    else if (tid < 384)
        ((float*)(smem + SM_ZN))[tid - 256] = g_z2[bm * 128 + (tid - 256)];

    // 3-stage cp.async tile loads (K chunks of 64 = 128B per row)
    {
        const char* As = (const char*)g_Xc + (size_t)(bn * 256) * ROWB;
        const char* Bs = (const char*)g_Zc + (size_t)(bm * 128) * ROWB;
#pragma unroll
        for (int s3 = 0; s3 < 3; ++s3) {
#pragma unroll
            for (int it = 0; it < 6; ++it) {
                if (it < 4) {                   // A: 2048 x 16B chunks
                    int i = tid + it * 512;
                    int row = i >> 3, c = i & 7;
                    CP16(sb + SM_A + s3 * ASTG + row * LDSW + c * 16,
                         As + (size_t)row * ROWB + s3 * 128 + c * 16);
                } else {                        // B: 1024 x 16B chunks
                    int j = tid + (it - 4) * 512;
                    int row = j >> 3, c = j & 7;
                    CP16(sb + SM_B + s3 * BSTG + row * LDSW + c * 16,
                         Bs + (size_t)row * ROWB + s3 * 128 + c * 16);
                }
            }
            asm volatile("cp.async.commit_group;" ::: "memory");
        }
    }

    // per-lane ldmatrix offsets (within a stage)
    const int l8 = lane & 7, sel = lane >> 3;
    uint32_t a_off[4], b_off[2];
#pragma unroll
    for (int mt = 0; mt < 4; ++mt) {
        int row = wm * 64 + mt * 16 + ((sel & 1) << 3) + l8;
        a_off[mt] = row * LDSW + ((sel >> 1) << 4);
    }
#pragma unroll
    for (int p = 0; p < 2; ++p) {
        int n = wn * 32 + p * 16 + ((sel >> 1) << 3) + l8;
        b_off[p] = n * LDSW + ((sel & 1) << 4);
    }

    float acc[4][4][4];
#pragma unroll
    for (int mt = 0; mt < 4; ++mt)
#pragma unroll
        for (int nt = 0; nt < 4; ++nt)
#pragma unroll
            for (int q = 0; q < 4; ++q) acc[mt][nt][q] = 0.0f;

    asm volatile("cp.async.wait_group 2;" ::: "memory");
    __syncthreads();
    stage_mma(sb + SM_A, sb + SM_B, a_off, b_off, acc);

    asm volatile("cp.async.wait_group 1;" ::: "memory");
    __syncthreads();
    stage_mma(sb + SM_A + ASTG, sb + SM_B + BSTG, a_off, b_off, acc);

    asm volatile("cp.async.wait_group 0;" ::: "memory");
    __syncthreads();
    stage_mma(sb + SM_A + 2 * ASTG, sb + SM_B + 2 * BSTG, a_off, b_off, acc);

    // ---- fused Matern epilogue ----
    const float ls = *lengthscale;
    const float sg = *sigma;
    const float cc = 1.7320508075688772f / ls;
    const float s2v = sg * sg;
    const float NL2E = -1.4426950408889634f;

    const int qrow = lane >> 2;          // 0..7
    const int qcol = (lane & 3) << 1;    // 0,2,4,6

    const float* xnS = (const float*)(smem + SM_XN);
    const float* znS = (const float*)(smem + SM_ZN);

    float2 znp[4];
#pragma unroll
    for (int nt = 0; nt < 4; ++nt)
        znp[nt] = *(const float2*)(znS + wn * 32 + nt * 8 + qcol);

#pragma unroll
    for (int mt = 0; mt < 4; ++mt) {
#pragma unroll
        for (int h = 0; h < 2; ++h) {
            const int rloc = wm * 64 + mt * 16 + h * 8 + qrow;
            const float xn = xnS[rloc];
            float* orow = out + (size_t)(bn * 256 + rloc) * M + bm * 128;
#pragma unroll
            for (int nt = 0; nt < 4; ++nt) {
                float d0 = acc[mt][nt][2 * h];
                float d1 = acc[mt][nt][2 * h + 1];
                float sq0 = fmaxf(fmaf(-2.0f, d0, xn + znp[nt].x), 1e-12f);
                float sq1 = fmaxf(fmaf(-2.0f, d1, xn + znp[nt].y), 1e-12f);
                float v0 = cc * fsqrt_ap(sq0);
                float v1 = cc * fsqrt_ap(sq1);
                float e0 = fex2(NL2E * v0);
                float e1 = fex2(NL2E * v1);
                float2 o;
                o.x = s2v * (1.0f + v0) * e0;
                o.y = s2v * (1.0f + v1) * e1;
                *(float2*)(orow + wn * 32 + nt * 8 + qcol) = o;
            }
        }
    }
}

extern "C" void kernel_launch(void* const* d_in, const int* in_sizes, int n_in,
                              void* d_out, int out_size) {
    const float* X = (const float*)d_in[0];
    const float* Z = (const float*)d_in[1];
    const float* sigma = (const float*)d_in[2];
    const float* lengthscale = (const float*)d_in[3];
    float* out = (float*)d_out;

    int N = in_sizes[0] / D_DIM;   // 8192
    int M = in_sizes[1] / D_DIM;   // 4096

    convert_kernel<<<((N + M) * 32 + 255) / 256, 256>>>(X, Z, N, M);

    cudaFuncSetAttribute(matern_hmma_kernel,
                         cudaFuncAttributeMaxDynamicSharedMemorySize, SM_TOTAL);
    dim3 grid(M / 128, N / 256);   // (32, 32)
    matern_hmma_kernel<<<grid, 512, SM_TOTAL>>>(sigma, lengthscale, out, M);
}